// round 6
// baseline (speedup 1.0000x reference)
#include <cuda_runtime.h>

#define N_NODES 100000
#define N_EDGES 1600000
#define HID 64
#define NGRAPH 4096
#define BN_EPS 1e-5f
#define SCAN_B 1024
#define SCAN_NB ((N_NODES + SCAN_B - 1) / SCAN_B)   // 98
#define GATH_GRID 1184
#define GATH_WARPS 8

// ---------------- scratch (device globals; no allocations) ----------------
__device__ __align__(16) float g_h[N_NODES * HID];    // linear output h (gather source)
__device__ __align__(16) float g_y[N_NODES * HID];    // post-relu layer output
__device__ int   g_cnt[N_NODES];                      // in-degree (histogram)
__device__ float g_dinv[N_NODES];
__device__ int   g_rowptr[N_NODES];
__device__ int   g_cursor[N_NODES];
__device__ __align__(8) int2 g_edge[N_EDGES];         // {src idx, weight bits} sorted by dst
__device__ int   g_blksum[SCAN_NB];
__device__ float g_stats[2][2 * HID];                 // ping-pong [sum(64), sumsq(64)]

// ---------------- CSR build ----------------
__global__ void hist_kernel(const int* __restrict__ dst) {
    int e = blockIdx.x * blockDim.x + threadIdx.x;
    if (e < N_EDGES) atomicAdd(&g_cnt[dst[e]], 1);
}

__global__ __launch_bounds__(SCAN_B) void scan1_kernel() {
    __shared__ int sm[SCAN_B];
    int t = threadIdx.x;
    int i = blockIdx.x * SCAN_B + t;
    int v = (i < N_NODES) ? g_cnt[i] : 0;
    sm[t] = v;
    __syncthreads();
    for (int off = 1; off < SCAN_B; off <<= 1) {
        int x = (t >= off) ? sm[t - off] : 0;
        __syncthreads();
        sm[t] += x;
        __syncthreads();
    }
    if (i < N_NODES) g_rowptr[i] = sm[t] - v;  // exclusive (block-local)
    if (t == SCAN_B - 1) g_blksum[blockIdx.x] = sm[t];
}

// parallel exclusive scan of the 98 block sums (one 128-thread block)
__global__ __launch_bounds__(128) void scan2_kernel() {
    __shared__ int sm[128];
    int t = threadIdx.x;
    int v = (t < SCAN_NB) ? g_blksum[t] : 0;
    sm[t] = v;
    __syncthreads();
    for (int off = 1; off < 128; off <<= 1) {
        int x = (t >= off) ? sm[t - off] : 0;
        __syncthreads();
        sm[t] += x;
        __syncthreads();
    }
    if (t < SCAN_NB) g_blksum[t] = sm[t] - v;
}

// scan finalize + cursor init + dinv (folded)
__global__ __launch_bounds__(SCAN_B) void scan3_kernel() {
    int i = blockIdx.x * SCAN_B + threadIdx.x;
    if (i < N_NODES) {
        int r = g_rowptr[i] + g_blksum[blockIdx.x];
        g_rowptr[i] = r;
        g_cursor[i] = r;
        g_dinv[i] = rsqrtf((float)g_cnt[i] + 1.f);
    }
}

__global__ void fill_kernel(const int* __restrict__ src, const int* __restrict__ dst) {
    int e = blockIdx.x * blockDim.x + threadIdx.x;
    if (e < N_EDGES) {
        int s = src[e];
        int d = dst[e];
        int pos = atomicAdd(&g_cursor[d], 1);
        float w = g_dinv[s] * g_dinv[d];
        g_edge[pos] = make_int2(s, __float_as_int(w));
    }
}

// ---------------- GEMM: h = X @ W ----------------
// Block: 256 threads, 64-node tile, each thread computes 4 nodes x 4 cols.
// FROM_Y: input = g_y with folded BN affine (computed inline from g_stats[rdp]).
// Every block also zeroes g_stats[wrp] (same value, benign race).
template <int IN, bool FROM_Y>
__global__ __launch_bounds__(256) void gemm_kernel(const float* __restrict__ X,
                                                   const float* __restrict__ W,
                                                   const float* __restrict__ gam,
                                                   const float* __restrict__ bet,
                                                   int rdp, int wrp) {
    __shared__ __align__(16) float Ws[IN * HID];
    __shared__ float Xs[64 * (IN + 1)];
    __shared__ float s_a[HID];
    __shared__ float s_dd[HID];

    int tid = threadIdx.x;

    if (tid < 2 * HID) g_stats[wrp][tid] = 0.f;

    for (int i = tid; i < IN * HID; i += 256) Ws[i] = W[i];
    if (FROM_Y && tid < HID) {
        float mean = g_stats[rdp][tid] * (1.f / N_NODES);
        float var  = g_stats[rdp][HID + tid] * (1.f / N_NODES) - mean * mean;
        float a = gam[tid] * rsqrtf(var + BN_EPS);
        s_a[tid]  = a;
        s_dd[tid] = bet[tid] - mean * a;
    }
    __syncthreads();

    int base = blockIdx.x * 64;
    for (int i = tid; i < 64 * IN; i += 256) {
        int n = i / IN, k = i - n * IN;
        int gn = base + n;
        float v = 0.f;
        if (gn < N_NODES) {
            if (FROM_Y) v = g_y[gn * HID + k] * s_a[k] + s_dd[k];
            else        v = X[gn * IN + k];
        }
        Xs[n * (IN + 1) + k] = v;
    }
    __syncthreads();

    int tx = tid & 15, ty = tid >> 4;
    int c0 = tx * 4, n0 = ty * 4;
    float4 a0 = {0.f, 0.f, 0.f, 0.f};
    float4 a1 = {0.f, 0.f, 0.f, 0.f};
    float4 a2 = {0.f, 0.f, 0.f, 0.f};
    float4 a3 = {0.f, 0.f, 0.f, 0.f};

#pragma unroll 5
    for (int k = 0; k < IN; k++) {
        float4 w = *(const float4*)&Ws[k * HID + c0];
        float x0 = Xs[(n0 + 0) * (IN + 1) + k];
        float x1 = Xs[(n0 + 1) * (IN + 1) + k];
        float x2 = Xs[(n0 + 2) * (IN + 1) + k];
        float x3 = Xs[(n0 + 3) * (IN + 1) + k];
        a0.x += x0 * w.x; a0.y += x0 * w.y; a0.z += x0 * w.z; a0.w += x0 * w.w;
        a1.x += x1 * w.x; a1.y += x1 * w.y; a1.z += x1 * w.z; a1.w += x1 * w.w;
        a2.x += x2 * w.x; a2.y += x2 * w.y; a2.z += x2 * w.z; a2.w += x2 * w.w;
        a3.x += x3 * w.x; a3.y += x3 * w.y; a3.z += x3 * w.z; a3.w += x3 * w.w;
    }

    float4 accs[4] = {a0, a1, a2, a3};
#pragma unroll
    for (int i = 0; i < 4; i++) {
        int gn = base + n0 + i;
        if (gn >= N_NODES) break;
        *(float4*)&g_h[gn * HID + c0] = accs[i];
    }
}

// ---------------- gather aggregation + relu + BN stats ----------------
// One full warp per node (no intra-warp divergence), 2 channels per lane
// (float2). Persistent grid-stride. Edge metadata staged by lanes 0-15 in
// 16-edge chunks, broadcast via width-32 shuffles. BN stats in registers,
// one smem reduce + 128 global reds per block at the end.
__global__ __launch_bounds__(256) void gather_kernel(const float* __restrict__ bias,
                                                     int wrp) {
    __shared__ float s_b[HID];
    __shared__ float sm_s[GATH_WARPS][HID];
    __shared__ float sm_q[GATH_WARPS][HID];

    int tid  = threadIdx.x;
    int warp = tid >> 5;
    int lane = tid & 31;
    int c2   = lane * 2;

    if (tid < HID) s_b[tid] = bias[tid];
    __syncthreads();
    float2 bb = *(const float2*)&s_b[c2];

    float2 s2 = {0.f, 0.f};
    float2 q2 = {0.f, 0.f};

    for (int n = blockIdx.x * GATH_WARPS + warp; n < N_NODES; n += GATH_GRID * GATH_WARPS) {
        float dv = g_dinv[n];
        float sn = dv * dv;

        float2 acc = *(const float2*)&g_h[n * HID + c2];
        acc.x = acc.x * sn + bb.x;
        acc.y = acc.y * sn + bb.y;

        int start = g_rowptr[n];
        int len   = g_cnt[n];

        for (int j0 = 0; j0 < len; j0 += 16) {
            int myj = j0 + lane;
            int sidx = 0;
            float w = 0.f;
            if (lane < 16 && myj < len) {
                int2 e = g_edge[start + myj];
                sidx = e.x;
                w = __int_as_float(e.y);
            }
#pragma unroll
            for (int j = 0; j < 16; j++) {
                int   s  = __shfl_sync(0xffffffffu, sidx, j);
                float wj = __shfl_sync(0xffffffffu, w,    j);
                float2 hv = *(const float2*)&g_h[s * HID + c2];
                acc.x += hv.x * wj;
                acc.y += hv.y * wj;
            }
        }

        acc.x = fmaxf(acc.x, 0.f);
        acc.y = fmaxf(acc.y, 0.f);
        *(float2*)&g_y[n * HID + c2] = acc;

        s2.x += acc.x; q2.x += acc.x * acc.x;
        s2.y += acc.y; q2.y += acc.y * acc.y;
    }

    sm_s[warp][c2 + 0] = s2.x; sm_q[warp][c2 + 0] = q2.x;
    sm_s[warp][c2 + 1] = s2.y; sm_q[warp][c2 + 1] = q2.y;
    __syncthreads();
    if (tid < HID) {
        float s = 0.f, q = 0.f;
#pragma unroll
        for (int r = 0; r < GATH_WARPS; r++) {
            s += sm_s[r][tid];
            q += sm_q[r][tid];
        }
        asm volatile("red.global.add.f32 [%0], %1;" :: "l"(&g_stats[wrp][tid]), "f"(s) : "memory");
        asm volatile("red.global.add.f32 [%0], %1;" :: "l"(&g_stats[wrp][HID + tid]), "f"(q) : "memory");
    }
}

// ---------------- global add pool (applies final BN affine) ----------------
// batch is sorted: each 16-lane group walks 16 consecutive nodes and flushes
// one red.v4 per graph-id change.
__global__ __launch_bounds__(256) void pool_kernel(const int* __restrict__ batch,
                                                   float* __restrict__ out,
                                                   const float* __restrict__ gam,
                                                   const float* __restrict__ bet) {
    __shared__ float s_a[HID];
    __shared__ float s_d[HID];
    int tid = threadIdx.x;
    if (tid < HID) {
        float mean = g_stats[1][tid] * (1.f / N_NODES);
        float var  = g_stats[1][HID + tid] * (1.f / N_NODES) - mean * mean;
        float a = gam[tid] * rsqrtf(var + BN_EPS);
        s_a[tid] = a;
        s_d[tid] = bet[tid] - mean * a;
    }
    __syncthreads();

    int grp = tid >> 4, lane = tid & 15;
    int c4 = lane * 4;
    float4 a4 = *(const float4*)&s_a[c4];
    float4 d4 = *(const float4*)&s_d[c4];

    int base = blockIdx.x * 256 + grp * 16;
    float4 run = {0.f, 0.f, 0.f, 0.f};
    int cur = -1;
    for (int i = 0; i < 16; i++) {
        int n = base + i;
        if (n >= N_NODES) break;
        int bt = batch[n];
        if (bt != cur) {
            if (cur >= 0) {
                asm volatile("red.global.add.v4.f32 [%0], {%1,%2,%3,%4};"
                             :: "l"(&out[cur * HID + c4]),
                                "f"(run.x), "f"(run.y), "f"(run.z), "f"(run.w) : "memory");
            }
            run.x = run.y = run.z = run.w = 0.f;
            cur = bt;
        }
        float4 v = *(const float4*)&g_y[n * HID + c4];
        run.x += v.x * a4.x + d4.x;
        run.y += v.y * a4.y + d4.y;
        run.z += v.z * a4.z + d4.z;
        run.w += v.w * a4.w + d4.w;
    }
    if (cur >= 0) {
        asm volatile("red.global.add.v4.f32 [%0], {%1,%2,%3,%4};"
                     :: "l"(&out[cur * HID + c4]),
                        "f"(run.x), "f"(run.y), "f"(run.z), "f"(run.w) : "memory");
    }
}

// ---------------- launch ----------------
extern "C" void kernel_launch(void* const* d_in, const int* in_sizes, int n_in,
                              void* d_out, int out_size) {
    const float* x     = (const float*)d_in[0];
    const int*   src   = (const int*)d_in[1];
    const int*   dst   = (const int*)d_in[2];
    const int*   batch = (const int*)d_in[3];
    const float* W[4];
    const float* b[4];
    const float* g[4];
    const float* be[4];
    for (int i = 0; i < 4; i++) {
        W[i]  = (const float*)d_in[4 + 4 * i];
        b[i]  = (const float*)d_in[5 + 4 * i];
        g[i]  = (const float*)d_in[6 + 4 * i];
        be[i] = (const float*)d_in[7 + 4 * i];
    }
    float* out = (float*)d_out;

    const int NB_NODES = (N_NODES + 255) / 256;   // 391
    const int NB_EDGES = (N_EDGES + 255) / 256;   // 6250
    const int NB_GEMM  = (N_NODES + 63) / 64;     // 1563

    cudaMemsetAsync(d_out, 0, (size_t)out_size * sizeof(float), 0);
    void* p_cnt = nullptr;
    cudaGetSymbolAddress(&p_cnt, g_cnt);
    cudaMemsetAsync(p_cnt, 0, N_NODES * sizeof(int), 0);

    // CSR build + norms
    hist_kernel<<<NB_EDGES, 256>>>(dst);
    scan1_kernel<<<SCAN_NB, SCAN_B>>>();
    scan2_kernel<<<1, 128>>>();
    scan3_kernel<<<SCAN_NB, SCAN_B>>>();
    fill_kernel<<<NB_EDGES, 256>>>(src, dst);

    // layer 1 (input: x, 75 features); stats parity: gather_l writes stats[l&1]
    gemm_kernel<75, false><<<NB_GEMM, 256>>>(x, W[0], nullptr, nullptr, 0, 0);
    gather_kernel<<<GATH_GRID, 256>>>(b[0], 0);

    // layers 2..4
    for (int l = 1; l < 4; l++) {
        gemm_kernel<64, true><<<NB_GEMM, 256>>>(nullptr, W[l], g[l - 1], be[l - 1],
                                                (l - 1) & 1, l & 1);
        gather_kernel<<<GATH_GRID, 256>>>(b[l], l & 1);
    }

    pool_kernel<<<NB_NODES, 256>>>(batch, out, g[3], be[3]);
}

// round 7
// speedup vs baseline: 1.0911x; 1.0911x over previous
#include <cuda_runtime.h>

#define N_NODES 100000
#define N_EDGES 1600000
#define HID 64
#define NGRAPH 4096
#define BN_EPS 1e-5f
#define SCAN_B 1024
#define SCAN_NB ((N_NODES + SCAN_B - 1) / SCAN_B)   // 98
#define N_TILES (N_NODES / 16)                      // 6250 (exact)
#define GATH_GRID 1184

// ---------------- scratch (device globals; no allocations) ----------------
__device__ __align__(16) float g_h[N_NODES * HID];    // linear output h (gather source)
__device__ __align__(16) float g_y[N_NODES * HID];    // post-relu layer output
__device__ int   g_cnt[N_NODES];                      // in-degree (histogram)
__device__ float g_dinv[N_NODES];
__device__ int   g_rowptr[N_NODES];
__device__ int   g_cursor[N_NODES];
__device__ __align__(8) int2 g_edge[N_EDGES];         // {src idx, weight bits} sorted by dst
__device__ int   g_blksum[SCAN_NB];
__device__ float g_stats[2][2 * HID];                 // ping-pong [sum(64), sumsq(64)]

// ---------------- f32x2 helpers ----------------
__device__ __forceinline__ void ffma2(unsigned long long& d,
                                      unsigned long long a,
                                      unsigned long long b) {
    asm("fma.rn.f32x2 %0, %1, %2, %0;" : "+l"(d) : "l"(a), "l"(b));
}
__device__ __forceinline__ unsigned long long fpack2(float x) {
    unsigned long long r;
    unsigned u = __float_as_uint(x);
    asm("mov.b64 %0, {%1, %1};" : "=l"(r) : "r"(u));
    return r;
}
__device__ __forceinline__ float2 funpack2(unsigned long long v) {
    unsigned lo, hi;
    asm("mov.b64 {%0, %1}, %2;" : "=r"(lo), "=r"(hi) : "l"(v));
    float2 f;
    f.x = __uint_as_float(lo);
    f.y = __uint_as_float(hi);
    return f;
}

// ---------------- CSR build ----------------
__global__ void hist_kernel(const int* __restrict__ dst) {
    int e = blockIdx.x * blockDim.x + threadIdx.x;
    if (e < N_EDGES) atomicAdd(&g_cnt[dst[e]], 1);
}

__global__ __launch_bounds__(SCAN_B) void scan1_kernel() {
    __shared__ int sm[SCAN_B];
    int t = threadIdx.x;
    int i = blockIdx.x * SCAN_B + t;
    int v = (i < N_NODES) ? g_cnt[i] : 0;
    sm[t] = v;
    __syncthreads();
    for (int off = 1; off < SCAN_B; off <<= 1) {
        int x = (t >= off) ? sm[t - off] : 0;
        __syncthreads();
        sm[t] += x;
        __syncthreads();
    }
    if (i < N_NODES) g_rowptr[i] = sm[t] - v;  // exclusive (block-local)
    if (t == SCAN_B - 1) g_blksum[blockIdx.x] = sm[t];
}

// scan finalize: each block re-scans the 98 block sums itself (O(98) smem work),
// then applies offset + inits cursor + dinv.  (Replaces scan2+scan3.)
__global__ __launch_bounds__(SCAN_B) void scan23_kernel() {
    __shared__ int sb[128];
    __shared__ int sv[128];
    int t = threadIdx.x;
    if (t < 128) {
        int v = (t < SCAN_NB) ? g_blksum[t] : 0;
        sb[t] = v;
        sv[t] = v;
    }
    __syncthreads();
    for (int off = 1; off < 128; off <<= 1) {
        int x = (t >= off && t < 128) ? sb[t - off] : 0;
        __syncthreads();
        if (t < 128) sb[t] += x;
        __syncthreads();
    }
    int offset = sb[blockIdx.x] - sv[blockIdx.x];  // exclusive prefix at this block
    int i = blockIdx.x * SCAN_B + t;
    if (i < N_NODES) {
        int r = g_rowptr[i] + offset;
        g_rowptr[i] = r;
        g_cursor[i] = r;
        g_dinv[i] = rsqrtf((float)g_cnt[i] + 1.f);
    }
}

__global__ void fill_kernel(const int* __restrict__ src, const int* __restrict__ dst) {
    int e = blockIdx.x * blockDim.x + threadIdx.x;
    if (e < N_EDGES) {
        int s = src[e];
        int d = dst[e];
        int pos = atomicAdd(&g_cursor[d], 1);
        float w = g_dinv[s] * g_dinv[d];
        g_edge[pos] = make_int2(s, __float_as_int(w));
    }
}

// ---------------- GEMM: h = X @ W (fp32x2 packed FFMA) ----------------
// Block: 256 threads, 64-node tile, each thread computes 4 nodes x 4 cols.
// Accumulators packed as column-pairs in 64-bit regs -> 8 FFMA2 per k.
template <int IN, bool FROM_Y>
__global__ __launch_bounds__(256) void gemm_kernel(const float* __restrict__ X,
                                                   const float* __restrict__ W,
                                                   const float* __restrict__ gam,
                                                   const float* __restrict__ bet,
                                                   int rdp, int wrp) {
    __shared__ __align__(16) float Ws[IN * HID];
    __shared__ float Xs[64 * (IN + 1)];
    __shared__ float s_a[HID];
    __shared__ float s_dd[HID];

    int tid = threadIdx.x;

    if (tid < 2 * HID) g_stats[wrp][tid] = 0.f;

    for (int i = tid; i < IN * HID; i += 256) Ws[i] = W[i];
    if (FROM_Y && tid < HID) {
        float mean = g_stats[rdp][tid] * (1.f / N_NODES);
        float var  = g_stats[rdp][HID + tid] * (1.f / N_NODES) - mean * mean;
        float a = gam[tid] * rsqrtf(var + BN_EPS);
        s_a[tid]  = a;
        s_dd[tid] = bet[tid] - mean * a;
    }
    __syncthreads();

    int base = blockIdx.x * 64;
    for (int i = tid; i < 64 * IN; i += 256) {
        int n = i / IN, k = i - n * IN;
        int gn = base + n;
        float v = 0.f;
        if (gn < N_NODES) {
            if (FROM_Y) v = g_y[gn * HID + k] * s_a[k] + s_dd[k];
            else        v = X[gn * IN + k];
        }
        Xs[n * (IN + 1) + k] = v;
    }
    __syncthreads();

    int tx = tid & 15, ty = tid >> 4;
    int c0 = tx * 4, n0 = ty * 4;

    // acc[node][pair]: pair 0 = cols (c0,c0+1), pair 1 = cols (c0+2,c0+3)
    unsigned long long acc[4][2] = {{0ull, 0ull}, {0ull, 0ull}, {0ull, 0ull}, {0ull, 0ull}};

#pragma unroll 5
    for (int k = 0; k < IN; k++) {
        ulonglong2 wq = *(const ulonglong2*)&Ws[k * HID + c0];
        unsigned long long x0 = fpack2(Xs[(n0 + 0) * (IN + 1) + k]);
        unsigned long long x1 = fpack2(Xs[(n0 + 1) * (IN + 1) + k]);
        unsigned long long x2 = fpack2(Xs[(n0 + 2) * (IN + 1) + k]);
        unsigned long long x3 = fpack2(Xs[(n0 + 3) * (IN + 1) + k]);
        ffma2(acc[0][0], x0, wq.x); ffma2(acc[0][1], x0, wq.y);
        ffma2(acc[1][0], x1, wq.x); ffma2(acc[1][1], x1, wq.y);
        ffma2(acc[2][0], x2, wq.x); ffma2(acc[2][1], x2, wq.y);
        ffma2(acc[3][0], x3, wq.x); ffma2(acc[3][1], x3, wq.y);
    }

#pragma unroll
    for (int i = 0; i < 4; i++) {
        int gn = base + n0 + i;
        if (gn >= N_NODES) break;
        float2 lo = funpack2(acc[i][0]);
        float2 hi = funpack2(acc[i][1]);
        float4 h;
        h.x = lo.x; h.y = lo.y; h.z = hi.x; h.w = hi.y;
        *(float4*)&g_h[gn * HID + c0] = h;
    }
}

// ---------------- gather aggregation + relu + BN stats ----------------
// Persistent grid-stride: 16 groups of 16 lanes per block, one node per group
// per tile (max bytes in flight per warp: LDG.128 rows). Edge metadata staged
// as packed int2. Inner chunk split 8/8 with group-uniform early exit to cut
// padded-edge waste. BN stats in registers; one smem reduce + 128 reds/block.
__global__ __launch_bounds__(256) void gather_kernel(const float* __restrict__ bias,
                                                     int wrp) {
    __shared__ float s_b[HID];
    __shared__ float sm_s[16][HID + 4];
    __shared__ float sm_q[16][HID + 4];

    int tid   = threadIdx.x;
    int grp   = tid >> 4;
    int lane  = tid & 15;
    unsigned hmask = 0xFFFFu << ((tid & 31) & 16);  // this half-warp's lanes
    int c4    = lane * 4;

    if (tid < HID) s_b[tid] = bias[tid];
    __syncthreads();
    float4 bb = *(const float4*)&s_b[c4];

    float4 s4 = {0.f, 0.f, 0.f, 0.f};
    float4 q4 = {0.f, 0.f, 0.f, 0.f};

    for (int tile = blockIdx.x; tile < N_TILES; tile += GATH_GRID) {
        int n = tile * 16 + grp;
        float dv = g_dinv[n];
        float sn = dv * dv;

        float4 acc = *(const float4*)&g_h[n * HID + c4];
        acc.x = acc.x * sn + bb.x;
        acc.y = acc.y * sn + bb.y;
        acc.z = acc.z * sn + bb.z;
        acc.w = acc.w * sn + bb.w;

        int start = g_rowptr[n];
        int len   = g_cnt[n];

        for (int j0 = 0; j0 < len; j0 += 16) {
            int myj = j0 + lane;
            int sidx = 0;
            float w = 0.f;
            if (myj < len) {
                int2 e = g_edge[start + myj];
                sidx = e.x;
                w = __int_as_float(e.y);
            }
#pragma unroll
            for (int j = 0; j < 8; j++) {
                int   s  = __shfl_sync(hmask, sidx, j, 16);
                float wj = __shfl_sync(hmask, w,    j, 16);
                float4 hv = *(const float4*)&g_h[s * HID + c4];
                acc.x += hv.x * wj;
                acc.y += hv.y * wj;
                acc.z += hv.z * wj;
                acc.w += hv.w * wj;
            }
            if (len > j0 + 8) {
#pragma unroll
                for (int j = 8; j < 16; j++) {
                    int   s  = __shfl_sync(hmask, sidx, j, 16);
                    float wj = __shfl_sync(hmask, w,    j, 16);
                    float4 hv = *(const float4*)&g_h[s * HID + c4];
                    acc.x += hv.x * wj;
                    acc.y += hv.y * wj;
                    acc.z += hv.z * wj;
                    acc.w += hv.w * wj;
                }
            }
        }

        acc.x = fmaxf(acc.x, 0.f);
        acc.y = fmaxf(acc.y, 0.f);
        acc.z = fmaxf(acc.z, 0.f);
        acc.w = fmaxf(acc.w, 0.f);
        *(float4*)&g_y[n * HID + c4] = acc;

        s4.x += acc.x; q4.x += acc.x * acc.x;
        s4.y += acc.y; q4.y += acc.y * acc.y;
        s4.z += acc.z; q4.z += acc.z * acc.z;
        s4.w += acc.w; q4.w += acc.w * acc.w;
    }

    sm_s[grp][c4 + 0] = s4.x; sm_q[grp][c4 + 0] = q4.x;
    sm_s[grp][c4 + 1] = s4.y; sm_q[grp][c4 + 1] = q4.y;
    sm_s[grp][c4 + 2] = s4.z; sm_q[grp][c4 + 2] = q4.z;
    sm_s[grp][c4 + 3] = s4.w; sm_q[grp][c4 + 3] = q4.w;
    __syncthreads();
    if (tid < HID) {
        float s = 0.f, q = 0.f;
#pragma unroll
        for (int r = 0; r < 16; r++) {
            s += sm_s[r][tid];
            q += sm_q[r][tid];
        }
        asm volatile("red.global.add.f32 [%0], %1;" :: "l"(&g_stats[wrp][tid]), "f"(s) : "memory");
        asm volatile("red.global.add.f32 [%0], %1;" :: "l"(&g_stats[wrp][HID + tid]), "f"(q) : "memory");
    }
}

// ---------------- global add pool (applies final BN affine) ----------------
__global__ __launch_bounds__(256) void pool_kernel(const int* __restrict__ batch,
                                                   float* __restrict__ out,
                                                   const float* __restrict__ gam,
                                                   const float* __restrict__ bet) {
    __shared__ float s_a[HID];
    __shared__ float s_d[HID];
    int tid = threadIdx.x;
    if (tid < HID) {
        float mean = g_stats[1][tid] * (1.f / N_NODES);
        float var  = g_stats[1][HID + tid] * (1.f / N_NODES) - mean * mean;
        float a = gam[tid] * rsqrtf(var + BN_EPS);
        s_a[tid] = a;
        s_d[tid] = bet[tid] - mean * a;
    }
    __syncthreads();

    int grp = tid >> 4, lane = tid & 15;
    int c4 = lane * 4;
    float4 a4 = *(const float4*)&s_a[c4];
    float4 d4 = *(const float4*)&s_d[c4];

    int base = blockIdx.x * 256 + grp * 16;
    float4 run = {0.f, 0.f, 0.f, 0.f};
    int cur = -1;
    for (int i = 0; i < 16; i++) {
        int n = base + i;
        if (n >= N_NODES) break;
        int bt = batch[n];
        if (bt != cur) {
            if (cur >= 0) {
                asm volatile("red.global.add.v4.f32 [%0], {%1,%2,%3,%4};"
                             :: "l"(&out[cur * HID + c4]),
                                "f"(run.x), "f"(run.y), "f"(run.z), "f"(run.w) : "memory");
            }
            run.x = run.y = run.z = run.w = 0.f;
            cur = bt;
        }
        float4 v = *(const float4*)&g_y[n * HID + c4];
        run.x += v.x * a4.x + d4.x;
        run.y += v.y * a4.y + d4.y;
        run.z += v.z * a4.z + d4.z;
        run.w += v.w * a4.w + d4.w;
    }
    if (cur >= 0) {
        asm volatile("red.global.add.v4.f32 [%0], {%1,%2,%3,%4};"
                     :: "l"(&out[cur * HID + c4]),
                        "f"(run.x), "f"(run.y), "f"(run.z), "f"(run.w) : "memory");
    }
}

// ---------------- launch ----------------
extern "C" void kernel_launch(void* const* d_in, const int* in_sizes, int n_in,
                              void* d_out, int out_size) {
    const float* x     = (const float*)d_in[0];
    const int*   src   = (const int*)d_in[1];
    const int*   dst   = (const int*)d_in[2];
    const int*   batch = (const int*)d_in[3];
    const float* W[4];
    const float* b[4];
    const float* g[4];
    const float* be[4];
    for (int i = 0; i < 4; i++) {
        W[i]  = (const float*)d_in[4 + 4 * i];
        b[i]  = (const float*)d_in[5 + 4 * i];
        g[i]  = (const float*)d_in[6 + 4 * i];
        be[i] = (const float*)d_in[7 + 4 * i];
    }
    float* out = (float*)d_out;

    const int NB_EDGES = (N_EDGES + 255) / 256;   // 6250
    const int NB_GEMM  = (N_NODES + 63) / 64;     // 1563
    const int NB_NODES = (N_NODES + 255) / 256;   // 391

    // launch order chosen so ncu (-s 5 -c 1) captures gemm1 (launch #6)
    void* p_cnt = nullptr;
    cudaGetSymbolAddress(&p_cnt, g_cnt);
    cudaMemsetAsync(p_cnt, 0, N_NODES * sizeof(int), 0);   // 1

    hist_kernel<<<NB_EDGES, 256>>>(dst);                   // 2
    scan1_kernel<<<SCAN_NB, SCAN_B>>>();                   // 3
    scan23_kernel<<<SCAN_NB, SCAN_B>>>();                  // 4
    fill_kernel<<<NB_EDGES, 256>>>(src, dst);              // 5

    // layer 1 (input: x, 75 features); stats parity: gather_l writes stats[l&1]
    gemm_kernel<75, false><<<NB_GEMM, 256>>>(x, W[0], nullptr, nullptr, 0, 0);  // 6 (captured)
    gather_kernel<<<GATH_GRID, 256>>>(b[0], 0);            // 7

    // layers 2..4
    for (int l = 1; l < 4; l++) {
        gemm_kernel<64, true><<<NB_GEMM, 256>>>(nullptr, W[l], g[l - 1], be[l - 1],
                                                (l - 1) & 1, l & 1);
        gather_kernel<<<GATH_GRID, 256>>>(b[l], l & 1);
    }

    cudaMemsetAsync(d_out, 0, (size_t)out_size * sizeof(float), 0);
    pool_kernel<<<NB_NODES, 256>>>(batch, out, g[3], be[3]);
}

// round 8
// speedup vs baseline: 1.0980x; 1.0063x over previous
#include <cuda_runtime.h>

#define N_NODES 100000
#define N_EDGES 1600000
#define HID 64
#define NGRAPH 4096
#define BN_EPS 1e-5f
#define SCAN_B 1024
#define SCAN_NB ((N_NODES + SCAN_B - 1) / SCAN_B)   // 98
#define N_TILES (N_NODES / 16)                      // 6250 (exact)
#define GATH_GRID 592

// ---------------- scratch (device globals; no allocations) ----------------
__device__ __align__(16) float g_h[N_NODES * HID];    // linear output h (gather source)
__device__ __align__(16) float g_y[N_NODES * HID];    // post-relu layer output
__device__ int   g_cnt[N_NODES];                      // in-degree (histogram)
__device__ float g_dinv[N_NODES];
__device__ int   g_rowptr[N_NODES];
__device__ int   g_cursor[N_NODES];
__device__ __align__(8) int2 g_edge[N_EDGES];         // {src idx, weight bits} sorted by dst
__device__ int   g_blksum[SCAN_NB];
__device__ float g_stats[2][2 * HID];                 // ping-pong [sum(64), sumsq(64)]

// ---------------- f32x2 helpers ----------------
__device__ __forceinline__ void ffma2(unsigned long long& d,
                                      unsigned long long a,
                                      unsigned long long b) {
    asm("fma.rn.f32x2 %0, %1, %2, %0;" : "+l"(d) : "l"(a), "l"(b));
}
__device__ __forceinline__ unsigned long long fpack2(float x) {
    unsigned long long r;
    unsigned u = __float_as_uint(x);
    asm("mov.b64 %0, {%1, %1};" : "=l"(r) : "r"(u));
    return r;
}
__device__ __forceinline__ float2 funpack2(unsigned long long v) {
    unsigned lo, hi;
    asm("mov.b64 {%0, %1}, %2;" : "=r"(lo), "=r"(hi) : "l"(v));
    float2 f;
    f.x = __uint_as_float(lo);
    f.y = __uint_as_float(hi);
    return f;
}

// ---------------- CSR build ----------------
__global__ void hist_kernel(const int* __restrict__ dst) {
    int e = blockIdx.x * blockDim.x + threadIdx.x;
    if (e < N_EDGES) {
        asm volatile("red.global.add.u32 [%0], %1;"
                     :: "l"(&g_cnt[dst[e]]), "r"(1) : "memory");
    }
}

__global__ __launch_bounds__(SCAN_B) void scan1_kernel() {
    __shared__ int sm[SCAN_B];
    int t = threadIdx.x;
    int i = blockIdx.x * SCAN_B + t;
    int v = (i < N_NODES) ? g_cnt[i] : 0;
    sm[t] = v;
    __syncthreads();
    for (int off = 1; off < SCAN_B; off <<= 1) {
        int x = (t >= off) ? sm[t - off] : 0;
        __syncthreads();
        sm[t] += x;
        __syncthreads();
    }
    if (i < N_NODES) g_rowptr[i] = sm[t] - v;  // exclusive (block-local)
    if (t == SCAN_B - 1) g_blksum[blockIdx.x] = sm[t];
}

// scan finalize: each block re-scans the 98 block sums itself (O(98) smem work),
// then applies offset + inits cursor + dinv.
__global__ __launch_bounds__(SCAN_B) void scan23_kernel() {
    __shared__ int sb[128];
    __shared__ int sv[128];
    int t = threadIdx.x;
    if (t < 128) {
        int v = (t < SCAN_NB) ? g_blksum[t] : 0;
        sb[t] = v;
        sv[t] = v;
    }
    __syncthreads();
    for (int off = 1; off < 128; off <<= 1) {
        int x = (t >= off && t < 128) ? sb[t - off] : 0;
        __syncthreads();
        if (t < 128) sb[t] += x;
        __syncthreads();
    }
    int offset = sb[blockIdx.x] - sv[blockIdx.x];  // exclusive prefix at this block
    int i = blockIdx.x * SCAN_B + t;
    if (i < N_NODES) {
        int r = g_rowptr[i] + offset;
        g_rowptr[i] = r;
        g_cursor[i] = r;
        g_dinv[i] = rsqrtf((float)g_cnt[i] + 1.f);
    }
}

__global__ void fill_kernel(const int* __restrict__ src, const int* __restrict__ dst) {
    int e = blockIdx.x * blockDim.x + threadIdx.x;
    if (e < N_EDGES) {
        int s = src[e];
        int d = dst[e];
        int pos = atomicAdd(&g_cursor[d], 1);
        float w = g_dinv[s] * g_dinv[d];
        g_edge[pos] = make_int2(s, __float_as_int(w));
    }
}

// ---------------- GEMM: h = X @ W (fp32x2 packed FFMA) ----------------
template <int IN, bool FROM_Y>
__global__ __launch_bounds__(256) void gemm_kernel(const float* __restrict__ X,
                                                   const float* __restrict__ W,
                                                   const float* __restrict__ gam,
                                                   const float* __restrict__ bet,
                                                   int rdp, int wrp) {
    __shared__ __align__(16) float Ws[IN * HID];
    __shared__ float Xs[64 * (IN + 1)];
    __shared__ float s_a[HID];
    __shared__ float s_dd[HID];

    int tid = threadIdx.x;

    if (tid < 2 * HID) g_stats[wrp][tid] = 0.f;

    for (int i = tid; i < IN * HID; i += 256) Ws[i] = W[i];
    if (FROM_Y && tid < HID) {
        float mean = g_stats[rdp][tid] * (1.f / N_NODES);
        float var  = g_stats[rdp][HID + tid] * (1.f / N_NODES) - mean * mean;
        float a = gam[tid] * rsqrtf(var + BN_EPS);
        s_a[tid]  = a;
        s_dd[tid] = bet[tid] - mean * a;
    }
    __syncthreads();

    int base = blockIdx.x * 64;
    for (int i = tid; i < 64 * IN; i += 256) {
        int n = i / IN, k = i - n * IN;
        int gn = base + n;
        float v = 0.f;
        if (gn < N_NODES) {
            if (FROM_Y) v = g_y[gn * HID + k] * s_a[k] + s_dd[k];
            else        v = X[gn * IN + k];
        }
        Xs[n * (IN + 1) + k] = v;
    }
    __syncthreads();

    int tx = tid & 15, ty = tid >> 4;
    int c0 = tx * 4, n0 = ty * 4;

    unsigned long long acc[4][2] = {{0ull, 0ull}, {0ull, 0ull}, {0ull, 0ull}, {0ull, 0ull}};

#pragma unroll 5
    for (int k = 0; k < IN; k++) {
        ulonglong2 wq = *(const ulonglong2*)&Ws[k * HID + c0];
        unsigned long long x0 = fpack2(Xs[(n0 + 0) * (IN + 1) + k]);
        unsigned long long x1 = fpack2(Xs[(n0 + 1) * (IN + 1) + k]);
        unsigned long long x2 = fpack2(Xs[(n0 + 2) * (IN + 1) + k]);
        unsigned long long x3 = fpack2(Xs[(n0 + 3) * (IN + 1) + k]);
        ffma2(acc[0][0], x0, wq.x); ffma2(acc[0][1], x0, wq.y);
        ffma2(acc[1][0], x1, wq.x); ffma2(acc[1][1], x1, wq.y);
        ffma2(acc[2][0], x2, wq.x); ffma2(acc[2][1], x2, wq.y);
        ffma2(acc[3][0], x3, wq.x); ffma2(acc[3][1], x3, wq.y);
    }

#pragma unroll
    for (int i = 0; i < 4; i++) {
        int gn = base + n0 + i;
        if (gn >= N_NODES) break;
        float2 lo = funpack2(acc[i][0]);
        float2 hi = funpack2(acc[i][1]);
        float4 h;
        h.x = lo.x; h.y = lo.y; h.z = hi.x; h.w = hi.y;
        *(float4*)&g_h[gn * HID + c0] = h;
    }
}

// ---------------- gather aggregation + relu + BN stats ----------------
// Persistent single-wave grid: 16 groups of 16 lanes per block, one node per
// group per tile. Metadata for the NEXT 16-edge chunk is prefetched before
// processing the current chunk (hides LDG.64 latency). Inner chunk has
// group-uniform early-outs every 4 edges; padded lanes carry w=0 (read node
// 0's row, L1-resident, contribute nothing).
__global__ __launch_bounds__(256) void gather_kernel(const float* __restrict__ bias,
                                                     int wrp) {
    __shared__ float s_b[HID];
    __shared__ float sm_s[16][HID + 4];
    __shared__ float sm_q[16][HID + 4];

    int tid   = threadIdx.x;
    int grp   = tid >> 4;
    int lane  = tid & 15;
    unsigned hmask = 0xFFFFu << ((tid & 31) & 16);  // this half-warp's lanes
    int c4    = lane * 4;

    if (tid < HID) s_b[tid] = bias[tid];
    __syncthreads();
    float4 bb = *(const float4*)&s_b[c4];

    float4 s4 = {0.f, 0.f, 0.f, 0.f};
    float4 q4 = {0.f, 0.f, 0.f, 0.f};

    for (int tile = blockIdx.x; tile < N_TILES; tile += GATH_GRID) {
        int n = tile * 16 + grp;
        float dv = g_dinv[n];
        float sn = dv * dv;

        float4 acc = *(const float4*)&g_h[n * HID + c4];
        acc.x = acc.x * sn + bb.x;
        acc.y = acc.y * sn + bb.y;
        acc.z = acc.z * sn + bb.z;
        acc.w = acc.w * sn + bb.w;

        int start = g_rowptr[n];
        int len   = g_cnt[n];

        // prefetch first metadata chunk
        int2 e = make_int2(0, 0);
        if (lane < len) e = g_edge[start + lane];

        for (int j0 = 0; j0 < len; j0 += 16) {
            int sidx = e.x;
            float w  = __int_as_float(e.y);
            // prefetch next chunk while current rows load
            e = make_int2(0, 0);
            int nj = j0 + 16 + lane;
            if (nj < len) e = g_edge[start + nj];

#pragma unroll
            for (int j = 0; j < 4; j++) {
                int   s  = __shfl_sync(hmask, sidx, j, 16);
                float wj = __shfl_sync(hmask, w,    j, 16);
                float4 hv = *(const float4*)&g_h[s * HID + c4];
                acc.x += hv.x * wj; acc.y += hv.y * wj;
                acc.z += hv.z * wj; acc.w += hv.w * wj;
            }
            if (len > j0 + 4) {
#pragma unroll
                for (int j = 4; j < 8; j++) {
                    int   s  = __shfl_sync(hmask, sidx, j, 16);
                    float wj = __shfl_sync(hmask, w,    j, 16);
                    float4 hv = *(const float4*)&g_h[s * HID + c4];
                    acc.x += hv.x * wj; acc.y += hv.y * wj;
                    acc.z += hv.z * wj; acc.w += hv.w * wj;
                }
            }
            if (len > j0 + 8) {
#pragma unroll
                for (int j = 8; j < 12; j++) {
                    int   s  = __shfl_sync(hmask, sidx, j, 16);
                    float wj = __shfl_sync(hmask, w,    j, 16);
                    float4 hv = *(const float4*)&g_h[s * HID + c4];
                    acc.x += hv.x * wj; acc.y += hv.y * wj;
                    acc.z += hv.z * wj; acc.w += hv.w * wj;
                }
            }
            if (len > j0 + 12) {
#pragma unroll
                for (int j = 12; j < 16; j++) {
                    int   s  = __shfl_sync(hmask, sidx, j, 16);
                    float wj = __shfl_sync(hmask, w,    j, 16);
                    float4 hv = *(const float4*)&g_h[s * HID + c4];
                    acc.x += hv.x * wj; acc.y += hv.y * wj;
                    acc.z += hv.z * wj; acc.w += hv.w * wj;
                }
            }
        }

        acc.x = fmaxf(acc.x, 0.f);
        acc.y = fmaxf(acc.y, 0.f);
        acc.z = fmaxf(acc.z, 0.f);
        acc.w = fmaxf(acc.w, 0.f);
        *(float4*)&g_y[n * HID + c4] = acc;

        s4.x += acc.x; q4.x += acc.x * acc.x;
        s4.y += acc.y; q4.y += acc.y * acc.y;
        s4.z += acc.z; q4.z += acc.z * acc.z;
        s4.w += acc.w; q4.w += acc.w * acc.w;
    }

    sm_s[grp][c4 + 0] = s4.x; sm_q[grp][c4 + 0] = q4.x;
    sm_s[grp][c4 + 1] = s4.y; sm_q[grp][c4 + 1] = q4.y;
    sm_s[grp][c4 + 2] = s4.z; sm_q[grp][c4 + 2] = q4.z;
    sm_s[grp][c4 + 3] = s4.w; sm_q[grp][c4 + 3] = q4.w;
    __syncthreads();
    if (tid < HID) {
        float s = 0.f, q = 0.f;
#pragma unroll
        for (int r = 0; r < 16; r++) {
            s += sm_s[r][tid];
            q += sm_q[r][tid];
        }
        asm volatile("red.global.add.f32 [%0], %1;" :: "l"(&g_stats[wrp][tid]), "f"(s) : "memory");
        asm volatile("red.global.add.f32 [%0], %1;" :: "l"(&g_stats[wrp][HID + tid]), "f"(q) : "memory");
    }
}

// ---------------- global add pool (applies final BN affine) ----------------
__global__ __launch_bounds__(256) void pool_kernel(const int* __restrict__ batch,
                                                   float* __restrict__ out,
                                                   const float* __restrict__ gam,
                                                   const float* __restrict__ bet) {
    __shared__ float s_a[HID];
    __shared__ float s_d[HID];
    int tid = threadIdx.x;
    if (tid < HID) {
        float mean = g_stats[1][tid] * (1.f / N_NODES);
        float var  = g_stats[1][HID + tid] * (1.f / N_NODES) - mean * mean;
        float a = gam[tid] * rsqrtf(var + BN_EPS);
        s_a[tid] = a;
        s_d[tid] = bet[tid] - mean * a;
    }
    __syncthreads();

    int grp = tid >> 4, lane = tid & 15;
    int c4 = lane * 4;
    float4 a4 = *(const float4*)&s_a[c4];
    float4 d4 = *(const float4*)&s_d[c4];

    int base = blockIdx.x * 256 + grp * 16;
    float4 run = {0.f, 0.f, 0.f, 0.f};
    int cur = -1;
    for (int i = 0; i < 16; i++) {
        int n = base + i;
        if (n >= N_NODES) break;
        int bt = batch[n];
        if (bt != cur) {
            if (cur >= 0) {
                asm volatile("red.global.add.v4.f32 [%0], {%1,%2,%3,%4};"
                             :: "l"(&out[cur * HID + c4]),
                                "f"(run.x), "f"(run.y), "f"(run.z), "f"(run.w) : "memory");
            }
            run.x = run.y = run.z = run.w = 0.f;
            cur = bt;
        }
        float4 v = *(const float4*)&g_y[n * HID + c4];
        run.x += v.x * a4.x + d4.x;
        run.y += v.y * a4.y + d4.y;
        run.z += v.z * a4.z + d4.z;
        run.w += v.w * a4.w + d4.w;
    }
    if (cur >= 0) {
        asm volatile("red.global.add.v4.f32 [%0], {%1,%2,%3,%4};"
                     :: "l"(&out[cur * HID + c4]),
                        "f"(run.x), "f"(run.y), "f"(run.z), "f"(run.w) : "memory");
    }
}

// ---------------- launch ----------------
extern "C" void kernel_launch(void* const* d_in, const int* in_sizes, int n_in,
                              void* d_out, int out_size) {
    const float* x     = (const float*)d_in[0];
    const int*   src   = (const int*)d_in[1];
    const int*   dst   = (const int*)d_in[2];
    const int*   batch = (const int*)d_in[3];
    const float* W[4];
    const float* b[4];
    const float* g[4];
    const float* be[4];
    for (int i = 0; i < 4; i++) {
        W[i]  = (const float*)d_in[4 + 4 * i];
        b[i]  = (const float*)d_in[5 + 4 * i];
        g[i]  = (const float*)d_in[6 + 4 * i];
        be[i] = (const float*)d_in[7 + 4 * i];
    }
    float* out = (float*)d_out;

    const int NB_EDGES = (N_EDGES + 255) / 256;   // 6250
    const int NB_GEMM  = (N_NODES + 63) / 64;     // 1563
    const int NB_NODES = (N_NODES + 255) / 256;   // 391

    void* p_cnt = nullptr;
    cudaGetSymbolAddress(&p_cnt, g_cnt);
    cudaMemsetAsync(p_cnt, 0, N_NODES * sizeof(int), 0);

    hist_kernel<<<NB_EDGES, 256>>>(dst);
    scan1_kernel<<<SCAN_NB, SCAN_B>>>();
    scan23_kernel<<<SCAN_NB, SCAN_B>>>();
    fill_kernel<<<NB_EDGES, 256>>>(src, dst);

    // layer 1 (input: x, 75 features); stats parity: gather_l writes stats[l&1]
    gemm_kernel<75, false><<<NB_GEMM, 256>>>(x, W[0], nullptr, nullptr, 0, 0);
    gather_kernel<<<GATH_GRID, 256>>>(b[0], 0);

    // layers 2..4
    for (int l = 1; l < 4; l++) {
        gemm_kernel<64, true><<<NB_GEMM, 256>>>(nullptr, W[l], g[l - 1], be[l - 1],
                                                (l - 1) & 1, l & 1);
        gather_kernel<<<GATH_GRID, 256>>>(b[l], l & 1);
    }

    cudaMemsetAsync(d_out, 0, (size_t)out_size * sizeof(float), 0);
    pool_kernel<<<NB_NODES, 256>>>(batch, out, g[3], be[3]);
}

// round 9
// speedup vs baseline: 1.1335x; 1.0323x over previous
#include <cuda_runtime.h>

#define N_NODES 100000
#define N_EDGES 1600000
#define HID 64
#define NGRAPH 4096
#define BN_EPS 1e-5f
#define SCAN_B 1024
#define SCAN_NB ((N_NODES + SCAN_B - 1) / SCAN_B)   // 98
#define N_TILES (N_NODES / 16)                      // 6250 (exact)
#define GATH_GRID 592

// ---------------- scratch (device globals; no allocations) ----------------
// g_h has one extra row (index N_NODES) kept all-zero: padded gather lanes
// point at it and contribute nothing.
__device__ __align__(16) float g_h[(N_NODES + 1) * HID]; // pre-scaled h' = h*dinv
__device__ __align__(16) float g_y[N_NODES * HID];       // post-relu layer output
__device__ int   g_cnt[N_NODES];                         // in-degree (histogram)
__device__ float g_dinv[N_NODES];
__device__ int   g_rowptr[N_NODES];
__device__ int   g_cursor[N_NODES];
__device__ int   g_eidx[N_EDGES];                        // src idx sorted by dst
__device__ int   g_blksum[SCAN_NB];
__device__ float g_stats[2][2 * HID];                    // ping-pong [sum, sumsq]

// ---------------- f32x2 helpers ----------------
__device__ __forceinline__ void ffma2(unsigned long long& d,
                                      unsigned long long a,
                                      unsigned long long b) {
    asm("fma.rn.f32x2 %0, %1, %2, %0;" : "+l"(d) : "l"(a), "l"(b));
}
__device__ __forceinline__ unsigned long long fpack2(float x) {
    unsigned long long r;
    unsigned u = __float_as_uint(x);
    asm("mov.b64 %0, {%1, %1};" : "=l"(r) : "r"(u));
    return r;
}
__device__ __forceinline__ float2 funpack2(unsigned long long v) {
    unsigned lo, hi;
    asm("mov.b64 {%0, %1}, %2;" : "=r"(lo), "=r"(hi) : "l"(v));
    float2 f;
    f.x = __uint_as_float(lo);
    f.y = __uint_as_float(hi);
    return f;
}

// ---------------- CSR build ----------------
__global__ void hist_kernel(const int* __restrict__ dst) {
    int e = blockIdx.x * blockDim.x + threadIdx.x;
    if (e < N_EDGES) {
        asm volatile("red.global.add.u32 [%0], %1;"
                     :: "l"(&g_cnt[dst[e]]), "r"(1) : "memory");
    }
}

__global__ __launch_bounds__(SCAN_B) void scan1_kernel() {
    __shared__ int sm[SCAN_B];
    int t = threadIdx.x;
    int i = blockIdx.x * SCAN_B + t;
    int v = (i < N_NODES) ? g_cnt[i] : 0;
    sm[t] = v;
    __syncthreads();
    for (int off = 1; off < SCAN_B; off <<= 1) {
        int x = (t >= off) ? sm[t - off] : 0;
        __syncthreads();
        sm[t] += x;
        __syncthreads();
    }
    if (i < N_NODES) g_rowptr[i] = sm[t] - v;  // exclusive (block-local)
    if (t == SCAN_B - 1) g_blksum[blockIdx.x] = sm[t];
}

// scan finalize: each block re-scans the 98 block sums itself, applies offset,
// inits cursor + dinv.
__global__ __launch_bounds__(SCAN_B) void scan23_kernel() {
    __shared__ int sb[128];
    __shared__ int sv[128];
    int t = threadIdx.x;
    if (t < 128) {
        int v = (t < SCAN_NB) ? g_blksum[t] : 0;
        sb[t] = v;
        sv[t] = v;
    }
    __syncthreads();
    for (int off = 1; off < 128; off <<= 1) {
        int x = (t >= off && t < 128) ? sb[t - off] : 0;
        __syncthreads();
        if (t < 128) sb[t] += x;
        __syncthreads();
    }
    int offset = sb[blockIdx.x] - sv[blockIdx.x];
    int i = blockIdx.x * SCAN_B + t;
    if (i < N_NODES) {
        int r = g_rowptr[i] + offset;
        g_rowptr[i] = r;
        g_cursor[i] = r;
        g_dinv[i] = rsqrtf((float)g_cnt[i] + 1.f);
    }
}

// fill: no dinv work, 4-byte scattered store only
__global__ void fill_kernel(const int* __restrict__ src, const int* __restrict__ dst) {
    int e = blockIdx.x * blockDim.x + threadIdx.x;
    if (e < N_EDGES) {
        int s = src[e];
        int d = dst[e];
        int pos = atomicAdd(&g_cursor[d], 1);
        g_eidx[pos] = s;
    }
}

// ---------------- GEMM: h' = (X @ W) * dinv[row] (fp32x2 packed FFMA) ------
template <int IN, bool FROM_Y>
__global__ __launch_bounds__(256) void gemm_kernel(const float* __restrict__ X,
                                                   const float* __restrict__ W,
                                                   const float* __restrict__ gam,
                                                   const float* __restrict__ bet,
                                                   int rdp, int wrp) {
    __shared__ __align__(16) float Ws[IN * HID];
    __shared__ float Xs[64 * (IN + 1)];
    __shared__ float s_a[HID];
    __shared__ float s_dd[HID];
    __shared__ float s_dv[64];

    int tid = threadIdx.x;

    if (tid < 2 * HID) g_stats[wrp][tid] = 0.f;

    for (int i = tid; i < IN * HID; i += 256) Ws[i] = W[i];
    if (FROM_Y && tid < HID) {
        float mean = g_stats[rdp][tid] * (1.f / N_NODES);
        float var  = g_stats[rdp][HID + tid] * (1.f / N_NODES) - mean * mean;
        float a = gam[tid] * rsqrtf(var + BN_EPS);
        s_a[tid]  = a;
        s_dd[tid] = bet[tid] - mean * a;
    }
    __syncthreads();

    int base = blockIdx.x * 64;
    if (tid < 64) {
        int gn = base + tid;
        s_dv[tid] = (gn < N_NODES) ? g_dinv[gn] : 0.f;
    }
    for (int i = tid; i < 64 * IN; i += 256) {
        int n = i / IN, k = i - n * IN;
        int gn = base + n;
        float v = 0.f;
        if (gn < N_NODES) {
            if (FROM_Y) v = g_y[gn * HID + k] * s_a[k] + s_dd[k];
            else        v = X[gn * IN + k];
        }
        Xs[n * (IN + 1) + k] = v;
    }
    __syncthreads();

    int tx = tid & 15, ty = tid >> 4;
    int c0 = tx * 4, n0 = ty * 4;

    unsigned long long acc[4][2] = {{0ull, 0ull}, {0ull, 0ull}, {0ull, 0ull}, {0ull, 0ull}};

#pragma unroll 5
    for (int k = 0; k < IN; k++) {
        ulonglong2 wq = *(const ulonglong2*)&Ws[k * HID + c0];
        unsigned long long x0 = fpack2(Xs[(n0 + 0) * (IN + 1) + k]);
        unsigned long long x1 = fpack2(Xs[(n0 + 1) * (IN + 1) + k]);
        unsigned long long x2 = fpack2(Xs[(n0 + 2) * (IN + 1) + k]);
        unsigned long long x3 = fpack2(Xs[(n0 + 3) * (IN + 1) + k]);
        ffma2(acc[0][0], x0, wq.x); ffma2(acc[0][1], x0, wq.y);
        ffma2(acc[1][0], x1, wq.x); ffma2(acc[1][1], x1, wq.y);
        ffma2(acc[2][0], x2, wq.x); ffma2(acc[2][1], x2, wq.y);
        ffma2(acc[3][0], x3, wq.x); ffma2(acc[3][1], x3, wq.y);
    }

#pragma unroll
    for (int i = 0; i < 4; i++) {
        int gn = base + n0 + i;
        if (gn >= N_NODES) break;
        float dv = s_dv[n0 + i];
        float2 lo = funpack2(acc[i][0]);
        float2 hi = funpack2(acc[i][1]);
        float4 h;
        h.x = lo.x * dv; h.y = lo.y * dv; h.z = hi.x * dv; h.w = hi.y * dv;
        *(float4*)&g_h[gn * HID + c0] = h;
    }
}

// ---------------- gather aggregation + relu + BN stats ----------------
// y[n] = relu( dinv[n]*(h'[n] + Sum h'[src]) + b ). No per-edge weight —
// the inner loop is pure row accumulation. Padded lanes index the zero row
// at N_NODES (L1-hot). Metadata prefetched one chunk ahead; group-uniform
// early-outs every 4 edges cut padded work.
__global__ __launch_bounds__(256) void gather_kernel(const float* __restrict__ bias,
                                                     int wrp) {
    __shared__ float s_b[HID];
    __shared__ float sm_s[16][HID + 4];
    __shared__ float sm_q[16][HID + 4];

    int tid   = threadIdx.x;
    int grp   = tid >> 4;
    int lane  = tid & 15;
    unsigned hmask = 0xFFFFu << ((tid & 31) & 16);  // this half-warp's lanes
    int c4    = lane * 4;

    if (tid < HID) s_b[tid] = bias[tid];
    __syncthreads();
    float4 bb = *(const float4*)&s_b[c4];

    float4 s4 = {0.f, 0.f, 0.f, 0.f};
    float4 q4 = {0.f, 0.f, 0.f, 0.f};

    for (int tile = blockIdx.x; tile < N_TILES; tile += GATH_GRID) {
        int n = tile * 16 + grp;
        float dv = g_dinv[n];

        float4 acc = *(const float4*)&g_h[n * HID + c4];  // self term h'[n]

        int start = g_rowptr[n];
        int len   = g_cnt[n];

        // prefetch first metadata chunk (pad -> zero row)
        int pre = (lane < len) ? g_eidx[start + lane] : N_NODES;

        for (int j0 = 0; j0 < len; j0 += 16) {
            int sidx = pre;
            int nj = j0 + 16 + lane;
            pre = (nj < len) ? g_eidx[start + nj] : N_NODES;

#pragma unroll
            for (int j = 0; j < 4; j++) {
                int s = __shfl_sync(hmask, sidx, j, 16);
                float4 hv = *(const float4*)&g_h[s * HID + c4];
                acc.x += hv.x; acc.y += hv.y;
                acc.z += hv.z; acc.w += hv.w;
            }
            if (len > j0 + 4) {
#pragma unroll
                for (int j = 4; j < 8; j++) {
                    int s = __shfl_sync(hmask, sidx, j, 16);
                    float4 hv = *(const float4*)&g_h[s * HID + c4];
                    acc.x += hv.x; acc.y += hv.y;
                    acc.z += hv.z; acc.w += hv.w;
                }
            }
            if (len > j0 + 8) {
#pragma unroll
                for (int j = 8; j < 12; j++) {
                    int s = __shfl_sync(hmask, sidx, j, 16);
                    float4 hv = *(const float4*)&g_h[s * HID + c4];
                    acc.x += hv.x; acc.y += hv.y;
                    acc.z += hv.z; acc.w += hv.w;
                }
            }
            if (len > j0 + 12) {
#pragma unroll
                for (int j = 12; j < 16; j++) {
                    int s = __shfl_sync(hmask, sidx, j, 16);
                    float4 hv = *(const float4*)&g_h[s * HID + c4];
                    acc.x += hv.x; acc.y += hv.y;
                    acc.z += hv.z; acc.w += hv.w;
                }
            }
        }

        acc.x = fmaxf(acc.x * dv + bb.x, 0.f);
        acc.y = fmaxf(acc.y * dv + bb.y, 0.f);
        acc.z = fmaxf(acc.z * dv + bb.z, 0.f);
        acc.w = fmaxf(acc.w * dv + bb.w, 0.f);
        *(float4*)&g_y[n * HID + c4] = acc;

        s4.x += acc.x; q4.x += acc.x * acc.x;
        s4.y += acc.y; q4.y += acc.y * acc.y;
        s4.z += acc.z; q4.z += acc.z * acc.z;
        s4.w += acc.w; q4.w += acc.w * acc.w;
    }

    sm_s[grp][c4 + 0] = s4.x; sm_q[grp][c4 + 0] = q4.x;
    sm_s[grp][c4 + 1] = s4.y; sm_q[grp][c4 + 1] = q4.y;
    sm_s[grp][c4 + 2] = s4.z; sm_q[grp][c4 + 2] = q4.z;
    sm_s[grp][c4 + 3] = s4.w; sm_q[grp][c4 + 3] = q4.w;
    __syncthreads();
    if (tid < HID) {
        float s = 0.f, q = 0.f;
#pragma unroll
        for (int r = 0; r < 16; r++) {
            s += sm_s[r][tid];
            q += sm_q[r][tid];
        }
        asm volatile("red.global.add.f32 [%0], %1;" :: "l"(&g_stats[wrp][tid]), "f"(s) : "memory");
        asm volatile("red.global.add.f32 [%0], %1;" :: "l"(&g_stats[wrp][HID + tid]), "f"(q) : "memory");
    }
}

// ---------------- global add pool (applies final BN affine) ----------------
__global__ __launch_bounds__(256) void pool_kernel(const int* __restrict__ batch,
                                                   float* __restrict__ out,
                                                   const float* __restrict__ gam,
                                                   const float* __restrict__ bet) {
    __shared__ float s_a[HID];
    __shared__ float s_d[HID];
    int tid = threadIdx.x;
    if (tid < HID) {
        float mean = g_stats[1][tid] * (1.f / N_NODES);
        float var  = g_stats[1][HID + tid] * (1.f / N_NODES) - mean * mean;
        float a = gam[tid] * rsqrtf(var + BN_EPS);
        s_a[tid] = a;
        s_d[tid] = bet[tid] - mean * a;
    }
    __syncthreads();

    int grp = tid >> 4, lane = tid & 15;
    int c4 = lane * 4;
    float4 a4 = *(const float4*)&s_a[c4];
    float4 d4 = *(const float4*)&s_d[c4];

    int base = blockIdx.x * 256 + grp * 16;
    float4 run = {0.f, 0.f, 0.f, 0.f};
    int cur = -1;
    for (int i = 0; i < 16; i++) {
        int n = base + i;
        if (n >= N_NODES) break;
        int bt = batch[n];
        if (bt != cur) {
            if (cur >= 0) {
                asm volatile("red.global.add.v4.f32 [%0], {%1,%2,%3,%4};"
                             :: "l"(&out[cur * HID + c4]),
                                "f"(run.x), "f"(run.y), "f"(run.z), "f"(run.w) : "memory");
            }
            run.x = run.y = run.z = run.w = 0.f;
            cur = bt;
        }
        float4 v = *(const float4*)&g_y[n * HID + c4];
        run.x += v.x * a4.x + d4.x;
        run.y += v.y * a4.y + d4.y;
        run.z += v.z * a4.z + d4.z;
        run.w += v.w * a4.w + d4.w;
    }
    if (cur >= 0) {
        asm volatile("red.global.add.v4.f32 [%0], {%1,%2,%3,%4};"
                     :: "l"(&out[cur * HID + c4]),
                        "f"(run.x), "f"(run.y), "f"(run.z), "f"(run.w) : "memory");
    }
}

// ---------------- launch ----------------
extern "C" void kernel_launch(void* const* d_in, const int* in_sizes, int n_in,
                              void* d_out, int out_size) {
    const float* x     = (const float*)d_in[0];
    const int*   src   = (const int*)d_in[1];
    const int*   dst   = (const int*)d_in[2];
    const int*   batch = (const int*)d_in[3];
    const float* W[4];
    const float* b[4];
    const float* g[4];
    const float* be[4];
    for (int i = 0; i < 4; i++) {
        W[i]  = (const float*)d_in[4 + 4 * i];
        b[i]  = (const float*)d_in[5 + 4 * i];
        g[i]  = (const float*)d_in[6 + 4 * i];
        be[i] = (const float*)d_in[7 + 4 * i];
    }
    float* out = (float*)d_out;

    const int NB_EDGES = (N_EDGES + 255) / 256;   // 6250
    const int NB_GEMM  = (N_NODES + 63) / 64;     // 1563
    const int NB_NODES = (N_NODES + 255) / 256;   // 391

    void* p_cnt = nullptr;
    cudaGetSymbolAddress(&p_cnt, g_cnt);
    cudaMemsetAsync(p_cnt, 0, N_NODES * sizeof(int), 0);

    hist_kernel<<<NB_EDGES, 256>>>(dst);
    scan1_kernel<<<SCAN_NB, SCAN_B>>>();
    scan23_kernel<<<SCAN_NB, SCAN_B>>>();   // produces dinv

    // gemm1 placed before fill so the ncu capture slot (#5/#6) lands on a hot
    // kernel; gemm1 only needs dinv (from scan23), not the CSR.
    gemm_kernel<75, false><<<NB_GEMM, 256>>>(x, W[0], nullptr, nullptr, 0, 0);
    fill_kernel<<<NB_EDGES, 256>>>(src, dst);

    // zero row N_NODES of g_h (target of padded gather lanes)
    void* p_h = nullptr;
    cudaGetSymbolAddress(&p_h, g_h);
    cudaMemsetAsync((char*)p_h + (size_t)N_NODES * HID * sizeof(float), 0,
                    HID * sizeof(float), 0);

    gather_kernel<<<GATH_GRID, 256>>>(b[0], 0);

    // layers 2..4
    for (int l = 1; l < 4; l++) {
        gemm_kernel<64, true><<<NB_GEMM, 256>>>(nullptr, W[l], g[l - 1], be[l - 1],
                                                (l - 1) & 1, l & 1);
        gather_kernel<<<GATH_GRID, 256>>>(b[l], l & 1);
    }

    cudaMemsetAsync(d_out, 0, (size_t)out_size * sizeof(float), 0);
    pool_kernel<<<NB_NODES, 256>>>(batch, out, g[3], be[3]);
}